// round 5
// baseline (speedup 1.0000x reference)
#include <cuda_runtime.h>
#include <cuda_bf16.h>
#include <cstdint>

typedef unsigned long long ull;

#define TT 512
#define BB 32
#define DD 1280
#define TBD (TT*BB*DD)   // 20971520
#define RNC 128
#define JPC 10
#define RTPB 256
#define NW 8
#define QSPAN 40

// -------- device scratch (no allocations allowed) --------
__device__ float g_xp[TBD];                    // x @ Wx^T + b
__device__ float g_h[2][BB*DD];                // h double buffer
__device__ unsigned g_flag[RNC];               // producer flags
__device__ float g_hlast_dummy[BB*DD];
__device__ __nv_bfloat16 g_xh[TBD];            // bf16 split of X
__device__ __nv_bfloat16 g_xl[TBD];
__device__ __nv_bfloat16 g_wh[DD*DD];          // bf16 split of Wx
__device__ __nv_bfloat16 g_wl[DD*DD];

// -------- packed f32x2 + memory helpers --------
__device__ __forceinline__ ull pack2(float lo, float hi){
  ull r; asm("mov.b64 %0, {%1, %2};" : "=l"(r) : "f"(lo), "f"(hi)); return r;
}
__device__ __forceinline__ float2 unpack2(ull v){
  float2 r; asm("mov.b64 {%0, %1}, %2;" : "=f"(r.x), "=f"(r.y) : "l"(v)); return r;
}
__device__ __forceinline__ void ffma2(ull& d, ull a, ull b){
  asm("fma.rn.f32x2 %0, %1, %2, %0;" : "+l"(d) : "l"(a), "l"(b));
}
__device__ __forceinline__ void ld_cg_v2u64(const void* p, ull& a, ull& b){
  asm volatile("ld.global.cg.v2.u64 {%0, %1}, [%2];" : "=l"(a), "=l"(b) : "l"(p));
}
__device__ __forceinline__ void st_cg_f32(float* p, float v){
  asm volatile("st.global.cg.f32 [%0], %1;" :: "l"(p), "f"(v) : "memory");
}
__device__ __forceinline__ unsigned ld_acq(const unsigned* p){
  unsigned v; asm volatile("ld.acquire.gpu.global.u32 %0, [%1];" : "=r"(v) : "l"(p)); return v;
}
__device__ __forceinline__ void st_rel(unsigned* p, unsigned v){
  asm volatile("st.release.gpu.global.u32 [%0], %1;" :: "l"(p), "r"(v) : "memory");
}

// -------- baseline-PTX tensor-core helpers (compile for compute_103) --------
__device__ __forceinline__ uint32_t smem_u32(const void* p){
  return (uint32_t)__cvta_generic_to_shared(p);
}
__device__ __forceinline__ void cp_async16(uint32_t dst, const void* src){
  asm volatile("cp.async.cg.shared.global [%0], [%1], 16;" :: "r"(dst), "l"(src));
}
__device__ __forceinline__ void cp_commit(){ asm volatile("cp.async.commit_group;" ::: "memory"); }
template<int N> __device__ __forceinline__ void cp_wait(){
  asm volatile("cp.async.wait_group %0;" :: "n"(N) : "memory");
}
__device__ __forceinline__ void ldsm_x4(uint32_t* r, uint32_t addr){
  asm volatile("ldmatrix.sync.aligned.m8n8.x4.shared.b16 {%0,%1,%2,%3}, [%4];"
    : "=r"(r[0]), "=r"(r[1]), "=r"(r[2]), "=r"(r[3]) : "r"(addr));
}
__device__ __forceinline__ void mma_bf16(float* c, const uint32_t* a,
                                         uint32_t b0, uint32_t b1){
  asm volatile(
    "mma.sync.aligned.m16n8k16.row.col.f32.bf16.bf16.f32 "
    "{%0,%1,%2,%3}, {%4,%5,%6,%7}, {%8,%9}, {%0,%1,%2,%3};"
    : "+f"(c[0]), "+f"(c[1]), "+f"(c[2]), "+f"(c[3])
    : "r"(a[0]), "r"(a[1]), "r"(a[2]), "r"(a[3]), "r"(b0), "r"(b1));
}

// ======================================================================
// Kernel A: split fp32 -> bf16 hi/lo pair
// ======================================================================
__global__ void convert_split(const float* __restrict__ src,
                              __nv_bfloat16* __restrict__ hi,
                              __nv_bfloat16* __restrict__ lo, size_t n)
{
  size_t stride = (size_t)gridDim.x * blockDim.x * 4;
  for (size_t i = ((size_t)blockIdx.x * blockDim.x + threadIdx.x) * 4; i < n; i += stride) {
    float4 v = *(const float4*)(src + i);
    __nv_bfloat162 h01 = __floats2bfloat162_rn(v.x, v.y);
    __nv_bfloat162 h23 = __floats2bfloat162_rn(v.z, v.w);
    __nv_bfloat162 l01 = __floats2bfloat162_rn(v.x - __bfloat162float(h01.x),
                                               v.y - __bfloat162float(h01.y));
    __nv_bfloat162 l23 = __floats2bfloat162_rn(v.z - __bfloat162float(h23.x),
                                               v.w - __bfloat162float(h23.y));
    *(__nv_bfloat162*)(hi + i)     = h01;
    *(__nv_bfloat162*)(hi + i + 2) = h23;
    *(__nv_bfloat162*)(lo + i)     = l01;
    *(__nv_bfloat162*)(lo + i + 2) = l23;
  }
}

// ======================================================================
// Kernel B: mma.sync bf16 GEMM  xp = X @ Wx^T + bias  (3-MMA fp32 split)
// CTA 128x128, 8 warps (4m x 2n), warp tile 32x64, K chunks of 32,
// double-buffered cp.async, padded smem rows (40 bf16 = 80B, LDSM
// conflict-free: r*80 mod 128 = {0,80,32,112,64,16,96,48}).
// ======================================================================
#define GK 32
#define NCHUNK (DD/GK)          // 40
#define LDS_ROW 40              // bf16 elements per smem row (80 bytes)
#define TILE_B (128*LDS_ROW*2)  // 10240 bytes per tile
#define STAGE_B (4*TILE_B)      // Ahi,Alo,Bhi,Blo = 40960 bytes

__global__ __launch_bounds__(256) void gemm_bf16(const float* __restrict__ bias)
{
  extern __shared__ char dynsm[];
  const uint32_t tb = smem_u32(dynsm);

  const int tid = threadIdx.x;
  const int wid = tid >> 5, lane = tid & 31;
  const int wm = wid & 3, wn = wid >> 2;     // warp grid 4(m) x 2(n)
  const int m0 = blockIdx.x * 128;
  const int n0 = blockIdx.y * 128;

  float acc[2][8][4];
  #pragma unroll
  for (int i = 0; i < 2; i++)
    #pragma unroll
    for (int j = 0; j < 8; j++)
      #pragma unroll
      for (int q = 0; q < 4; q++) acc[i][j][q] = 0.f;

  // loader: 4 tiles x 512 16B-slots, 8 cp.async per thread per chunk
  auto load_chunk = [&](int kc, int s) {
    const int k0 = kc * GK;
    const char* srcs[4] = {
      (const char*)(g_xh + (size_t)m0 * DD + k0),
      (const char*)(g_xl + (size_t)m0 * DD + k0),
      (const char*)(g_wh + (size_t)n0 * DD + k0),
      (const char*)(g_wl + (size_t)n0 * DD + k0) };
    #pragma unroll
    for (int tl = 0; tl < 4; ++tl) {
      uint32_t base = tb + s * STAGE_B + tl * TILE_B;
      const char* sp = srcs[tl];
      #pragma unroll
      for (int it = 0; it < 2; ++it) {
        int idx = tid + it * 256;            // 512 slots
        int row = idx >> 2, c = idx & 3;     // 4 x 16B per 64B row
        cp_async16(base + row * (LDS_ROW * 2) + c * 16,
                   sp + (size_t)row * (DD * 2) + c * 16);
      }
    }
    cp_commit();
  };

  // ldmatrix source addresses (element units -> *2 bytes)
  // A (16x16, row-major): rows lanes 0-15 -> [row0+lane][ks], 16-31 -> [..][ks+8]
  auto addrA = [&](int tile_off, int s, int row0, int ks) -> uint32_t {
    int row = row0 + (lane & 15);
    int col = ks + ((lane >> 4) << 3);
    return tb + s * STAGE_B + tile_off + (row * LDS_ROW + col) * 2;
  };
  // B (n16 x k16, W[n][k] k-contig = col-major KxN):
  // m0: n0:8/k0:8, m1: n0:8/k8:16, m2: n8:16/k0:8, m3: n8:16/k8:16
  auto addrB = [&](int tile_off, int s, int nrow0, int ks) -> uint32_t {
    int row = nrow0 + ((lane >> 4) << 3) + (lane & 7);
    int col = ks + (((lane >> 3) & 1) << 3);
    return tb + s * STAGE_B + tile_off + (row * LDS_ROW + col) * 2;
  };

  load_chunk(0, 0);
  load_chunk(1, 1);

  for (int kc = 0; kc < NCHUNK; ++kc) {
    const int s = kc & 1;
    if (kc >= NCHUNK - 2) cp_wait<0>(); else cp_wait<1>();
    __syncthreads();                          // chunk kc resident, all warps ready

    #pragma unroll
    for (int ks = 0; ks < GK; ks += 16) {
      uint32_t ah[2][4], al[2][4];
      #pragma unroll
      for (int mi = 0; mi < 2; ++mi) {
        ldsm_x4(ah[mi], addrA(0,        s, wm * 32 + mi * 16, ks));
        ldsm_x4(al[mi], addrA(TILE_B,   s, wm * 32 + mi * 16, ks));
      }
      #pragma unroll
      for (int nb = 0; nb < 4; ++nb) {
        uint32_t bh[4], bl[4];
        ldsm_x4(bh, addrB(2 * TILE_B, s, wn * 64 + nb * 16, ks));
        ldsm_x4(bl, addrB(3 * TILE_B, s, wn * 64 + nb * 16, ks));
        #pragma unroll
        for (int mi = 0; mi < 2; ++mi) {
          float* c0 = acc[mi][nb * 2];
          float* c1 = acc[mi][nb * 2 + 1];
          mma_bf16(c0, ah[mi], bh[0], bh[1]);   // hi*hi
          mma_bf16(c1, ah[mi], bh[2], bh[3]);
          mma_bf16(c0, ah[mi], bl[0], bl[1]);   // hi*lo
          mma_bf16(c1, ah[mi], bl[2], bl[3]);
          mma_bf16(c0, al[mi], bh[0], bh[1]);   // lo*hi
          mma_bf16(c1, al[mi], bh[2], bh[3]);
        }
      }
    }
    __syncthreads();                          // all warps done reading buffer s
    if (kc + 2 < NCHUNK) load_chunk(kc + 2, s);
  }

  // epilogue: frag (mi,ni): c0,c1 -> (m = base+lane/4,   n = nb+2*(lane%4))
  //                         c2,c3 -> (m = base+lane/4+8, same n)
  const int mrow = lane >> 2, ncol = (lane & 3) * 2;
  #pragma unroll
  for (int mi = 0; mi < 2; ++mi) {
    #pragma unroll
    for (int ni = 0; ni < 8; ++ni) {
      int m = m0 + wm * 32 + mi * 16 + mrow;
      int n = n0 + wn * 64 + ni * 8 + ncol;
      float b0 = bias[n], b1 = bias[n + 1];
      *(float2*)&g_xp[(size_t)m * DD + n] =
          make_float2(acc[mi][ni][0] + b0, acc[mi][ni][1] + b1);
      *(float2*)&g_xp[(size_t)(m + 8) * DD + n] =
          make_float2(acc[mi][ni][2] + b0, acc[mi][ni][3] + b1);
    }
  }
}

// ======================================================================
// Kernel 0: reset flags + transpose h0 into interleaved layout
// ======================================================================
__global__ void init_state(const float* __restrict__ h0)
{
  int idx = blockIdx.x * blockDim.x + threadIdx.x;
  int stride = gridDim.x * blockDim.x;
  if (idx < RNC) g_flag[idx] = 0;
  for (int i = idx; i < BB * DD; i += stride) {
    int b = i / DD, k = i % DD;
    g_h[0][(k >> 2) * 128 + b * 4 + (k & 3)] = h0[i];
  }
}

// ======================================================================
// Kernel 2: persistent recurrence, dataflow-synced (unchanged from R3).
// ======================================================================
__global__ __launch_bounds__(RTPB, 1) void recurrence(
    const float* __restrict__ zseq, const float* __restrict__ Wh,
    float* __restrict__ out, float* __restrict__ hlast)
{
  extern __shared__ float sm[];
  float* ws   = sm;
  float* redb = sm + JPC * DD;

  const int tid = threadIdx.x, bid = blockIdx.x;
  const int lane = tid & 31, wid = tid >> 5;
  const int j0 = bid * JPC;

  {
    float4* ws4 = (float4*)ws;
    const float4* W4 = (const float4*)Wh;
    for (int i = tid; i < JPC * (DD/4); i += RTPB) {
      int j = i / (DD/4), kq = i % (DD/4);
      ws4[kq * JPC + j] = W4[(size_t)(j0 + j) * (DD/4) + kq];
    }
  }

  const int b1 = tid / JPC, jj1 = tid % JPC;
  const int o1  = b1 * DD + j0 + jj1;
  const int ha1 = ((j0 + jj1) >> 2) * 128 + b1 * 4 + ((j0 + jj1) & 3);
  const bool has2 = (tid < JPC * BB - RTPB);
  const int task2 = tid + RTPB;
  const int b2 = task2 / JPC, jj2 = task2 % JPC;
  const int o2  = b2 * DD + j0 + jj2;
  const int ha2 = ((j0 + jj2) >> 2) * 128 + b2 * 4 + ((j0 + jj2) & 3);

  __syncthreads();

  const int kq0 = wid * QSPAN;
  const unsigned* myflag = g_flag + wid * 16 + (lane & 15);

  size_t base = 0;
  float xp1 = __ldcs(&g_xp[o1]);
  float z1  = __ldcs(&zseq[o1]);
  float xp2 = has2 ? __ldcs(&g_xp[o2]) : 0.f;
  float z2  = has2 ? __ldcs(&zseq[o2]) : 0.f;

  for (int t = 0; t < TT; ++t) {
    const float* hc = g_h[t & 1];
    float*       hn = g_h[(t & 1) ^ 1];
    float sz1 = z1 / (1.0f + __expf(-z1));
    float sz2 = has2 ? (z2 / (1.0f + __expf(-z2))) : 0.f;

    if (t > 0) {
      while (true) {
        unsigned v = ld_acq(myflag);
        if (__all_sync(0xffffffffu, v >= (unsigned)t)) break;
        __nanosleep(32);
      }
    }

    ull acc[JPC];
    #pragma unroll
    for (int j = 0; j < JPC; ++j) acc[j] = 0ull;

    const char* hp = (const char*)(hc + (size_t)kq0 * 128 + lane * 4);
    ull h0r[4], h1r[4];
    #pragma unroll
    for (int d = 0; d < 4; ++d) ld_cg_v2u64(hp + (size_t)d * 512, h0r[d], h1r[d]);
    #pragma unroll 4
    for (int q = 0; q < QSPAN; ++q) {
      ull h0 = h0r[q & 3], h1 = h1r[q & 3];
      if (q + 4 < QSPAN) ld_cg_v2u64(hp + (size_t)(q + 4) * 512, h0r[q & 3], h1r[q & 3]);
      const ulonglong2* wq = (const ulonglong2*)(ws + (size_t)(kq0 + q) * (JPC * 4));
      #pragma unroll
      for (int j = 0; j < JPC; ++j) {
        ulonglong2 wv = wq[j];
        ffma2(acc[j], h0, wv.x);
        ffma2(acc[j], h1, wv.y);
      }
    }

    {
      float s[JPC];
      #pragma unroll
      for (int j = 0; j < JPC; ++j) { float2 p = unpack2(acc[j]); s[j] = p.x + p.y; }
      float* rp = redb + wid * 384 + lane * 12;
      *(float4*)(rp + 0) = make_float4(s[0], s[1], s[2], s[3]);
      *(float4*)(rp + 4) = make_float4(s[4], s[5], s[6], s[7]);
      *(float2*)(rp + 8) = make_float2(s[8], s[9]);
    }
    __syncthreads();

    {
      float s = 0.f;
      #pragma unroll
      for (int w = 0; w < NW; ++w) s += redb[w * 384 + b1 * 12 + jj1];
      float h = tanhf(xp1 + s);
      out[base + o1] = h * sz1;
      st_cg_f32(&hn[ha1], h);
      if (t == TT - 1) hlast[o1] = h;
    }
    if (has2) {
      float s = 0.f;
      #pragma unroll
      for (int w = 0; w < NW; ++w) s += redb[w * 384 + b2 * 12 + jj2];
      float h = tanhf(xp2 + s);
      out[base + o2] = h * sz2;
      st_cg_f32(&hn[ha2], h);
      if (t == TT - 1) hlast[o2] = h;
    }
    __syncthreads();

    if (tid == 0) st_rel(&g_flag[bid], (unsigned)(t + 1));

    base += (size_t)BB * DD;
    if (t + 1 < TT) {
      xp1 = __ldcs(&g_xp[base + o1]);
      z1  = __ldcs(&zseq[base + o1]);
      if (has2) { xp2 = __ldcs(&g_xp[base + o2]); z2 = __ldcs(&zseq[base + o2]); }
    }
  }
}

// ======================================================================
extern "C" void kernel_launch(void* const* d_in, const int* in_sizes, int n_in,
                              void* d_out, int out_size)
{
  const float* x    = (const float*)d_in[0];
  const float* z    = (const float*)d_in[1];
  const float* h0   = (const float*)d_in[2];
  const float* Wx   = (const float*)d_in[3];
  const float* Wh   = (const float*)d_in[4];
  const float* bias = (const float*)d_in[5];

  float* out = (float*)d_out;
  void* dummy = nullptr;
  cudaGetSymbolAddress(&dummy, g_hlast_dummy);
  float* hlast = (out_size >= (int)(TBD + BB * DD)) ? (out + TBD) : (float*)dummy;

  void *p_xh, *p_xl, *p_wh, *p_wl;
  cudaGetSymbolAddress(&p_xh, g_xh); cudaGetSymbolAddress(&p_xl, g_xl);
  cudaGetSymbolAddress(&p_wh, g_wh); cudaGetSymbolAddress(&p_wl, g_wl);

  const int rec_smem  = (JPC * DD + NW * 384) * (int)sizeof(float);
  const int gemm_smem = 2 * STAGE_B;           // 81920 bytes
  cudaFuncSetAttribute(recurrence, cudaFuncAttributeMaxDynamicSharedMemorySize, rec_smem);
  cudaFuncSetAttribute(gemm_bf16,  cudaFuncAttributeMaxDynamicSharedMemorySize, gemm_smem);

  init_state<<<40, 256>>>(h0);
  convert_split<<<2048, 256>>>(x,  (__nv_bfloat16*)p_xh, (__nv_bfloat16*)p_xl, (size_t)TBD);
  convert_split<<<512, 256>>>(Wx, (__nv_bfloat16*)p_wh, (__nv_bfloat16*)p_wl, (size_t)DD*DD);
  gemm_bf16<<<dim3(128, 10), 256, gemm_smem>>>(bias);
  recurrence<<<RNC, RTPB, rec_smem>>>(z, Wh, out, hlast);
}

// round 6
// speedup vs baseline: 1.6860x; 1.6860x over previous
#include <cuda_runtime.h>
#include <cuda_bf16.h>
#include <cstdint>

typedef unsigned long long ull;

#define TT 512
#define BB 32
#define DD 1280
#define TBD (TT*BB*DD)   // 20971520
#define RNC 128
#define JPC 10
#define RTPB 256
#define NW 8
#define QSPAN 40
#define PFD 8            // h-load prefetch depth (QSPAN % PFD == 0)

// -------- device scratch (no allocations allowed) --------
__device__ float g_xp[TBD];                    // x @ Wx^T + b
__device__ float g_h[2][BB*DD];                // h double buffer
__device__ unsigned g_flag[RNC*32];            // producer flags, 128B apart (own L2 sector)
__device__ float g_hlast_dummy[BB*DD];
__device__ __nv_bfloat16 g_xh[TBD];            // bf16 split of X
__device__ __nv_bfloat16 g_xl[TBD];
__device__ __nv_bfloat16 g_wh[DD*DD];          // bf16 split of Wx
__device__ __nv_bfloat16 g_wl[DD*DD];

// -------- packed f32x2 + memory helpers --------
__device__ __forceinline__ ull pack2(float lo, float hi){
  ull r; asm("mov.b64 %0, {%1, %2};" : "=l"(r) : "f"(lo), "f"(hi)); return r;
}
__device__ __forceinline__ float2 unpack2(ull v){
  float2 r; asm("mov.b64 {%0, %1}, %2;" : "=f"(r.x), "=f"(r.y) : "l"(v)); return r;
}
__device__ __forceinline__ void ffma2(ull& d, ull a, ull b){
  asm("fma.rn.f32x2 %0, %1, %2, %0;" : "+l"(d) : "l"(a), "l"(b));
}
__device__ __forceinline__ void ld_cg_v2u64(const void* p, ull& a, ull& b){
  asm volatile("ld.global.cg.v2.u64 {%0, %1}, [%2];" : "=l"(a), "=l"(b) : "l"(p));
}
__device__ __forceinline__ void st_cg_f32(float* p, float v){
  asm volatile("st.global.cg.f32 [%0], %1;" :: "l"(p), "f"(v) : "memory");
}
__device__ __forceinline__ unsigned ld_acq(const unsigned* p){
  unsigned v; asm volatile("ld.acquire.gpu.global.u32 %0, [%1];" : "=r"(v) : "l"(p)); return v;
}
__device__ __forceinline__ void st_rel(unsigned* p, unsigned v){
  asm volatile("st.release.gpu.global.u32 [%0], %1;" :: "l"(p), "r"(v) : "memory");
}
// fast tanh: 1 - 2/(e^{2x}+1); exact saturation at +/-inf, ~1e-6 abs error
__device__ __forceinline__ float fast_tanh(float x){
  float e = __expf(2.0f * x);
  return 1.0f - __fdividef(2.0f, e + 1.0f);
}

// -------- baseline-PTX tensor-core helpers (compile for compute_103) --------
__device__ __forceinline__ uint32_t smem_u32(const void* p){
  return (uint32_t)__cvta_generic_to_shared(p);
}
__device__ __forceinline__ void cp_async16(uint32_t dst, const void* src){
  asm volatile("cp.async.cg.shared.global [%0], [%1], 16;" :: "r"(dst), "l"(src));
}
__device__ __forceinline__ void cp_commit(){ asm volatile("cp.async.commit_group;" ::: "memory"); }
template<int N> __device__ __forceinline__ void cp_wait(){
  asm volatile("cp.async.wait_group %0;" :: "n"(N) : "memory");
}
__device__ __forceinline__ void ldsm_x4(uint32_t* r, uint32_t addr){
  asm volatile("ldmatrix.sync.aligned.m8n8.x4.shared.b16 {%0,%1,%2,%3}, [%4];"
    : "=r"(r[0]), "=r"(r[1]), "=r"(r[2]), "=r"(r[3]) : "r"(addr));
}
__device__ __forceinline__ void mma_bf16(float* c, const uint32_t* a,
                                         uint32_t b0, uint32_t b1){
  asm volatile(
    "mma.sync.aligned.m16n8k16.row.col.f32.bf16.bf16.f32 "
    "{%0,%1,%2,%3}, {%4,%5,%6,%7}, {%8,%9}, {%0,%1,%2,%3};"
    : "+f"(c[0]), "+f"(c[1]), "+f"(c[2]), "+f"(c[3])
    : "r"(a[0]), "r"(a[1]), "r"(a[2]), "r"(a[3]), "r"(b0), "r"(b1));
}

// ======================================================================
// Kernel A: split fp32 -> bf16 hi/lo pair
// ======================================================================
__global__ void convert_split(const float* __restrict__ src,
                              __nv_bfloat16* __restrict__ hi,
                              __nv_bfloat16* __restrict__ lo, size_t n)
{
  size_t stride = (size_t)gridDim.x * blockDim.x * 4;
  for (size_t i = ((size_t)blockIdx.x * blockDim.x + threadIdx.x) * 4; i < n; i += stride) {
    float4 v = *(const float4*)(src + i);
    __nv_bfloat162 h01 = __floats2bfloat162_rn(v.x, v.y);
    __nv_bfloat162 h23 = __floats2bfloat162_rn(v.z, v.w);
    __nv_bfloat162 l01 = __floats2bfloat162_rn(v.x - __bfloat162float(h01.x),
                                               v.y - __bfloat162float(h01.y));
    __nv_bfloat162 l23 = __floats2bfloat162_rn(v.z - __bfloat162float(h23.x),
                                               v.w - __bfloat162float(h23.y));
    *(__nv_bfloat162*)(hi + i)     = h01;
    *(__nv_bfloat162*)(hi + i + 2) = h23;
    *(__nv_bfloat162*)(lo + i)     = l01;
    *(__nv_bfloat162*)(lo + i + 2) = l23;
  }
}

// ======================================================================
// Kernel B: mma.sync bf16 GEMM  xp = X @ Wx^T + bias  (3-MMA fp32 split)
// (unchanged from R5: measured 727us, tensor 56.6%)
// ======================================================================
#define GK 32
#define NCHUNK (DD/GK)          // 40
#define LDS_ROW 40              // bf16 elements per smem row (80 bytes)
#define TILE_B (128*LDS_ROW*2)  // 10240 bytes per tile
#define STAGE_B (4*TILE_B)      // Ahi,Alo,Bhi,Blo = 40960 bytes

__global__ __launch_bounds__(256) void gemm_bf16(const float* __restrict__ bias)
{
  extern __shared__ char dynsm[];
  const uint32_t tb = smem_u32(dynsm);

  const int tid = threadIdx.x;
  const int wid = tid >> 5, lane = tid & 31;
  const int wm = wid & 3, wn = wid >> 2;
  const int m0 = blockIdx.x * 128;
  const int n0 = blockIdx.y * 128;

  float acc[2][8][4];
  #pragma unroll
  for (int i = 0; i < 2; i++)
    #pragma unroll
    for (int j = 0; j < 8; j++)
      #pragma unroll
      for (int q = 0; q < 4; q++) acc[i][j][q] = 0.f;

  auto load_chunk = [&](int kc, int s) {
    const int k0 = kc * GK;
    const char* srcs[4] = {
      (const char*)(g_xh + (size_t)m0 * DD + k0),
      (const char*)(g_xl + (size_t)m0 * DD + k0),
      (const char*)(g_wh + (size_t)n0 * DD + k0),
      (const char*)(g_wl + (size_t)n0 * DD + k0) };
    #pragma unroll
    for (int tl = 0; tl < 4; ++tl) {
      uint32_t base = tb + s * STAGE_B + tl * TILE_B;
      const char* sp = srcs[tl];
      #pragma unroll
      for (int it = 0; it < 2; ++it) {
        int idx = tid + it * 256;
        int row = idx >> 2, c = idx & 3;
        cp_async16(base + row * (LDS_ROW * 2) + c * 16,
                   sp + (size_t)row * (DD * 2) + c * 16);
      }
    }
    cp_commit();
  };

  auto addrA = [&](int tile_off, int s, int row0, int ks) -> uint32_t {
    int row = row0 + (lane & 15);
    int col = ks + ((lane >> 4) << 3);
    return tb + s * STAGE_B + tile_off + (row * LDS_ROW + col) * 2;
  };
  auto addrB = [&](int tile_off, int s, int nrow0, int ks) -> uint32_t {
    int row = nrow0 + ((lane >> 4) << 3) + (lane & 7);
    int col = ks + (((lane >> 3) & 1) << 3);
    return tb + s * STAGE_B + tile_off + (row * LDS_ROW + col) * 2;
  };

  load_chunk(0, 0);
  load_chunk(1, 1);

  for (int kc = 0; kc < NCHUNK; ++kc) {
    const int s = kc & 1;
    if (kc >= NCHUNK - 2) cp_wait<0>(); else cp_wait<1>();
    __syncthreads();

    #pragma unroll
    for (int ks = 0; ks < GK; ks += 16) {
      uint32_t ah[2][4], al[2][4];
      #pragma unroll
      for (int mi = 0; mi < 2; ++mi) {
        ldsm_x4(ah[mi], addrA(0,        s, wm * 32 + mi * 16, ks));
        ldsm_x4(al[mi], addrA(TILE_B,   s, wm * 32 + mi * 16, ks));
      }
      #pragma unroll
      for (int nb = 0; nb < 4; ++nb) {
        uint32_t bh[4], bl[4];
        ldsm_x4(bh, addrB(2 * TILE_B, s, wn * 64 + nb * 16, ks));
        ldsm_x4(bl, addrB(3 * TILE_B, s, wn * 64 + nb * 16, ks));
        #pragma unroll
        for (int mi = 0; mi < 2; ++mi) {
          float* c0 = acc[mi][nb * 2];
          float* c1 = acc[mi][nb * 2 + 1];
          mma_bf16(c0, ah[mi], bh[0], bh[1]);
          mma_bf16(c1, ah[mi], bh[2], bh[3]);
          mma_bf16(c0, ah[mi], bl[0], bl[1]);
          mma_bf16(c1, ah[mi], bl[2], bl[3]);
          mma_bf16(c0, al[mi], bh[0], bh[1]);
          mma_bf16(c1, al[mi], bh[2], bh[3]);
        }
      }
    }
    __syncthreads();
    if (kc + 2 < NCHUNK) load_chunk(kc + 2, s);
  }

  const int mrow = lane >> 2, ncol = (lane & 3) * 2;
  #pragma unroll
  for (int mi = 0; mi < 2; ++mi) {
    #pragma unroll
    for (int ni = 0; ni < 8; ++ni) {
      int m = m0 + wm * 32 + mi * 16 + mrow;
      int n = n0 + wn * 64 + ni * 8 + ncol;
      float b0 = bias[n], b1 = bias[n + 1];
      *(float2*)&g_xp[(size_t)m * DD + n] =
          make_float2(acc[mi][ni][0] + b0, acc[mi][ni][1] + b1);
      *(float2*)&g_xp[(size_t)(m + 8) * DD + n] =
          make_float2(acc[mi][ni][2] + b0, acc[mi][ni][3] + b1);
    }
  }
}

// ======================================================================
// Kernel 0: reset flags + transpose h0 into interleaved layout
// ======================================================================
__global__ void init_state(const float* __restrict__ h0)
{
  int idx = blockIdx.x * blockDim.x + threadIdx.x;
  int stride = gridDim.x * blockDim.x;
  if (idx < RNC * 32) g_flag[idx] = 0;
  for (int i = idx; i < BB * DD; i += stride) {
    int b = i / DD, k = i % DD;
    g_h[0][(k >> 2) * 128 + b * 4 + (k & 3)] = h0[i];
  }
}

// ======================================================================
// Kernel 2: persistent recurrence, dataflow-synced.
// R6: sector-spread flags, publish-before-output epilogue, fast tanh,
// depth-8 h-load pipeline.
// ======================================================================
__global__ __launch_bounds__(RTPB, 1) void recurrence(
    const float* __restrict__ zseq, const float* __restrict__ Wh,
    float* __restrict__ out, float* __restrict__ hlast)
{
  extern __shared__ float sm[];
  float* ws   = sm;
  float* redb = sm + JPC * DD;

  const int tid = threadIdx.x, bid = blockIdx.x;
  const int lane = tid & 31, wid = tid >> 5;
  const int j0 = bid * JPC;

  {
    float4* ws4 = (float4*)ws;
    const float4* W4 = (const float4*)Wh;
    for (int i = tid; i < JPC * (DD/4); i += RTPB) {
      int j = i / (DD/4), kq = i % (DD/4);
      ws4[kq * JPC + j] = W4[(size_t)(j0 + j) * (DD/4) + kq];
    }
  }

  const int b1 = tid / JPC, jj1 = tid % JPC;
  const int o1  = b1 * DD + j0 + jj1;
  const int ha1 = ((j0 + jj1) >> 2) * 128 + b1 * 4 + ((j0 + jj1) & 3);
  const bool has2 = (tid < JPC * BB - RTPB);
  const int task2 = tid + RTPB;
  const int b2 = task2 / JPC, jj2 = task2 % JPC;
  const int o2  = b2 * DD + j0 + jj2;
  const int ha2 = ((j0 + jj2) >> 2) * 128 + b2 * 4 + ((j0 + jj2) & 3);

  __syncthreads();

  const int kq0 = wid * QSPAN;
  const unsigned* myflag = g_flag + (wid * 16 + (lane & 15)) * 32;  // 16 producers, own sectors

  size_t base = 0;
  float xp1 = __ldcs(&g_xp[o1]);
  float z1  = __ldcs(&zseq[o1]);
  float xp2 = has2 ? __ldcs(&g_xp[o2]) : 0.f;
  float z2  = has2 ? __ldcs(&zseq[o2]) : 0.f;

  for (int t = 0; t < TT; ++t) {
    const float* hc = g_h[t & 1];
    float*       hn = g_h[(t & 1) ^ 1];
    float sz1 = __fdividef(z1, 1.0f + __expf(-z1));        // silu off critical path
    float sz2 = has2 ? __fdividef(z2, 1.0f + __expf(-z2)) : 0.f;

    // ---- per-warp dataflow wait: my 16 producers have written h_t ----
    if (t > 0) {
      while (true) {
        unsigned v = ld_acq(myflag);
        if (__all_sync(0xffffffffu, v >= (unsigned)t)) break;
        __nanosleep(32);
      }
    }

    // ---- partial dot products: lane = batch, 10 columns, 160 k per warp ----
    ull acc[JPC];
    #pragma unroll
    for (int j = 0; j < JPC; ++j) acc[j] = 0ull;

    const char* hp = (const char*)(hc + (size_t)kq0 * 128 + lane * 4);
    ull h0r[PFD], h1r[PFD];
    #pragma unroll
    for (int d = 0; d < PFD; ++d) ld_cg_v2u64(hp + (size_t)d * 512, h0r[d], h1r[d]);
    #pragma unroll 8
    for (int q = 0; q < QSPAN; ++q) {
      ull h0 = h0r[q & (PFD-1)], h1 = h1r[q & (PFD-1)];
      if (q + PFD < QSPAN)
        ld_cg_v2u64(hp + (size_t)(q + PFD) * 512, h0r[q & (PFD-1)], h1r[q & (PFD-1)]);
      const ulonglong2* wq = (const ulonglong2*)(ws + (size_t)(kq0 + q) * (JPC * 4));
      #pragma unroll
      for (int j = 0; j < JPC; ++j) {
        ulonglong2 wv = wq[j];
        ffma2(acc[j], h0, wv.x);
        ffma2(acc[j], h1, wv.y);
      }
    }

    // ---- stage partials: redb[wid][lane][j] ----
    {
      float s[JPC];
      #pragma unroll
      for (int j = 0; j < JPC; ++j) { float2 p = unpack2(acc[j]); s[j] = p.x + p.y; }
      float* rp = redb + wid * 384 + lane * 12;
      *(float4*)(rp + 0) = make_float4(s[0], s[1], s[2], s[3]);
      *(float4*)(rp + 4) = make_float4(s[4], s[5], s[6], s[7]);
      *(float2*)(rp + 8) = make_float2(s[8], s[9]);
    }
    __syncthreads();   // A: partials visible; all warps passed flag polls => hn overwrite safe

    // ---- critical-path epilogue: reduce, tanh, store h ONLY ----
    float hv1, hv2 = 0.f;
    {
      float s = 0.f;
      #pragma unroll
      for (int w = 0; w < NW; ++w) s += redb[w * 384 + b1 * 12 + jj1];
      hv1 = fast_tanh(xp1 + s);
      st_cg_f32(&hn[ha1], hv1);
    }
    if (has2) {
      float s = 0.f;
      #pragma unroll
      for (int w = 0; w < NW; ++w) s += redb[w * 384 + b2 * 12 + jj2];
      hv2 = fast_tanh(xp2 + s);
      st_cg_f32(&hn[ha2], hv2);
    }
    __syncthreads();   // B: all hn stores issued, redb reads done

    // ---- publish immediately (peers only need hn, not out) ----
    if (tid == 0) st_rel(&g_flag[bid * 32], (unsigned)(t + 1));

    // ---- off-path work: gated output, hlast, next-step prefetch ----
    out[base + o1] = hv1 * sz1;
    if (has2) out[base + o2] = hv2 * sz2;
    if (t == TT - 1) {
      hlast[o1] = hv1;
      if (has2) hlast[o2] = hv2;
    }
    base += (size_t)BB * DD;
    if (t + 1 < TT) {
      xp1 = __ldcs(&g_xp[base + o1]);
      z1  = __ldcs(&zseq[base + o1]);
      if (has2) { xp2 = __ldcs(&g_xp[base + o2]); z2 = __ldcs(&zseq[base + o2]); }
    }
  }
}

// ======================================================================
extern "C" void kernel_launch(void* const* d_in, const int* in_sizes, int n_in,
                              void* d_out, int out_size)
{
  const float* x    = (const float*)d_in[0];
  const float* z    = (const float*)d_in[1];
  const float* h0   = (const float*)d_in[2];
  const float* Wx   = (const float*)d_in[3];
  const float* Wh   = (const float*)d_in[4];
  const float* bias = (const float*)d_in[5];

  float* out = (float*)d_out;
  void* dummy = nullptr;
  cudaGetSymbolAddress(&dummy, g_hlast_dummy);
  float* hlast = (out_size >= (int)(TBD + BB * DD)) ? (out + TBD) : (float*)dummy;

  void *p_xh, *p_xl, *p_wh, *p_wl;
  cudaGetSymbolAddress(&p_xh, g_xh); cudaGetSymbolAddress(&p_xl, g_xl);
  cudaGetSymbolAddress(&p_wh, g_wh); cudaGetSymbolAddress(&p_wl, g_wl);

  const int rec_smem  = (JPC * DD + NW * 384) * (int)sizeof(float);
  const int gemm_smem = 2 * STAGE_B;
  cudaFuncSetAttribute(recurrence, cudaFuncAttributeMaxDynamicSharedMemorySize, rec_smem);
  cudaFuncSetAttribute(gemm_bf16,  cudaFuncAttributeMaxDynamicSharedMemorySize, gemm_smem);

  init_state<<<40, 256>>>(h0);
  convert_split<<<2048, 256>>>(x,  (__nv_bfloat16*)p_xh, (__nv_bfloat16*)p_xl, (size_t)TBD);
  convert_split<<<512, 256>>>(Wx, (__nv_bfloat16*)p_wh, (__nv_bfloat16*)p_wl, (size_t)DD*DD);
  gemm_bf16<<<dim3(128, 10), 256, gemm_smem>>>(bias);
  recurrence<<<RNC, RTPB, rec_smem>>>(z, Wh, out, hlast);
}